// round 7
// baseline (speedup 1.0000x reference)
#include <cuda_runtime.h>

#define BB 16
#define SS 256
#define VV 32000
#define HH 1024
#define EE 512
#define DQD 512
#define TT 255
#define KG 3584
#define G4 4096
#define XLEN 2560
#define NBLK 148

// ---------------- device scratch ----------------
__device__ __align__(16) float g_hidden[BB*SS*HH];
__device__ __align__(16) float g_hsproj[BB*SS*HH];
__device__ __align__(16) float g_h[BB*HH];
__device__ __align__(16) float g_c[BB*HH];
__device__ __align__(16) float g_h0[BB*HH];
__device__ __align__(16) float g_hW[BB*HH];
__device__ __align__(16) float g_score[BB*SS];
__device__ __align__(16) float g_gates[BB*G4];
__device__ __align__(16) float g_weighted[BB*HH];
__device__ __align__(16) float g_Wcat[(size_t)G4*KG];
__device__ __align__(16) float g_bias_sum[G4];
__device__ __align__(16) float g_we[(size_t)TT*BB*EE];
__device__ __align__(16) float g_Z[(size_t)TT*BB*2*HH];
__device__ unsigned g_cnt = 0;
__device__ volatile unsigned g_gen = 0;

__device__ __forceinline__ float fast_tanh(float x) {
    float e = __expf(2.0f * x);
    return 1.0f - __fdividef(2.0f, e + 1.0f);
}
__device__ __forceinline__ float fast_sig(float x) {
    return __fdividef(1.0f, 1.0f + __expf(-x));
}

// ---------------- prep (verbatim from verified round-3) ----------------
__global__ void k_prep(const int* __restrict__ inp, const float* __restrict__ embedW,
                       const float* __restrict__ W_ih, const float* __restrict__ W_hh,
                       const float* __restrict__ b_ih, const float* __restrict__ b_hh,
                       float* __restrict__ out)
{
    const long long N1 = (long long)G4 * KG;
    const long long N2 = N1 + G4;
    const long long N3 = N2 + (long long)TT * BB * EE;
    const long long N4 = N3 + (long long)BB * VV;
    for (long long i = (long long)blockIdx.x * blockDim.x + threadIdx.x;
         i < N4; i += (long long)gridDim.x * blockDim.x) {
        if (i < N1) {
            int n = (int)(i / KG), k = (int)(i % KG);
            g_Wcat[i] = (k < XLEN) ? W_ih[(long long)n * XLEN + k]
                                   : W_hh[(long long)n * HH + (k - XLEN)];
        } else if (i < N2) {
            int n = (int)(i - N1);
            g_bias_sum[n] = b_ih[n] + b_hh[n];
        } else if (i < N3) {
            long long j = i - N2;
            int t = (int)(j / (BB * EE));
            int r = (int)(j % (BB * EE));
            int b = r / EE, e = r % EE;
            int tok = inp[b * SS + t];
            g_we[j] = embedW[(long long)tok * EE + e];
        } else {
            long long j = i - N3;
            int b = (int)(j / VV);
            int vv = (int)(j % VV);
            out[(long long)b * SS * VV + vv] = 0.0f;
        }
    }
}

__global__ void k_init_h()
{
    int idx = blockIdx.x * blockDim.x + threadIdx.x;
    int b = idx >> 10, h = idx & 1023;
    float c0 = g_hidden[((b * SS + (SS - 1)) << 10) + h];
    g_c[idx] = c0;
    float h0 = tanhf(c0);
    g_h0[idx] = h0;
    g_h[idx] = h0;
    g_hW[idx] = 0.0f;
}

// ---------------- big tiled fp32 GEMM (verbatim from verified round-3) ----------------
template<int BIAS_EN, int SCATTER>
__global__ __launch_bounds__(256)
void k_biggemm(const float* __restrict__ A, int lda,
               const float* __restrict__ W, int ldw, int woff,
               const float* __restrict__ bias,
               float* __restrict__ C, int ldc, int M, int K)
{
    __shared__ float As[16][132];
    __shared__ float Bs[16][68];
    int tid = threadIdx.x;
    int m0 = blockIdx.x * 128;
    int n0 = blockIdx.y * 64;
    int ar  = tid >> 1;
    int akc = (tid & 1) * 8;
    int wn  = tid >> 2;
    int wkc = (tid & 3) * 4;
    int tx  = tid & 15;
    int ty  = tid >> 4;

    float acc[8][4];
#pragma unroll
    for (int i = 0; i < 8; i++)
#pragma unroll
        for (int j = 0; j < 4; j++) acc[i][j] = 0.0f;

    bool aok = (m0 + ar) < M;
    const float* Arow = A + (size_t)(m0 + ar) * lda;
    const float* Wrow = W + (size_t)(n0 + wn) * ldw + woff;

    for (int k0 = 0; k0 < K; k0 += 16) {
        float4 av0, av1;
        if (aok) {
            av0 = *(const float4*)(Arow + k0 + akc);
            av1 = *(const float4*)(Arow + k0 + akc + 4);
        } else {
            av0 = make_float4(0.f, 0.f, 0.f, 0.f);
            av1 = av0;
        }
        float4 wv = *(const float4*)(Wrow + k0 + wkc);
        __syncthreads();
        As[akc + 0][ar] = av0.x; As[akc + 1][ar] = av0.y;
        As[akc + 2][ar] = av0.z; As[akc + 3][ar] = av0.w;
        As[akc + 4][ar] = av1.x; As[akc + 5][ar] = av1.y;
        As[akc + 6][ar] = av1.z; As[akc + 7][ar] = av1.w;
        Bs[wkc + 0][wn] = wv.x;  Bs[wkc + 1][wn] = wv.y;
        Bs[wkc + 2][wn] = wv.z;  Bs[wkc + 3][wn] = wv.w;
        __syncthreads();
#pragma unroll
        for (int kk = 0; kk < 16; kk++) {
            float4 a0 = *(const float4*)&As[kk][ty * 8];
            float4 a1 = *(const float4*)&As[kk][ty * 8 + 4];
            float4 bv = *(const float4*)&Bs[kk][tx * 4];
            float ra[8] = {a0.x, a0.y, a0.z, a0.w, a1.x, a1.y, a1.z, a1.w};
            float rb[4] = {bv.x, bv.y, bv.z, bv.w};
#pragma unroll
            for (int i = 0; i < 8; i++)
#pragma unroll
                for (int j = 0; j < 4; j++)
                    acc[i][j] = fmaf(ra[i], rb[j], acc[i][j]);
        }
    }
#pragma unroll
    for (int i = 0; i < 8; i++) {
        int m = m0 + ty * 8 + i;
        if (m < M) {
            float4 r;
            r.x = acc[i][0]; r.y = acc[i][1]; r.z = acc[i][2]; r.w = acc[i][3];
            if (BIAS_EN) {
                int n = n0 + tx * 4;
                r.x += bias[n]; r.y += bias[n + 1]; r.z += bias[n + 2]; r.w += bias[n + 3];
            }
            float* dst;
            if (SCATTER) {
                int trow = m >> 4, b = m & 15;
                dst = C + (size_t)(b * SS + trow + 1) * ldc + n0 + tx * 4;
            } else {
                dst = C + (size_t)m * ldc + n0 + tx * 4;
            }
            *(float4*)dst = r;
        }
    }
}

// ---------------- persistent recurrence kernel ----------------
__device__ __forceinline__ void gbar() {
    __syncthreads();
    if (threadIdx.x == 0) {
        __threadfence();
        unsigned g = g_gen;
        if (atomicAdd(&g_cnt, 1u) == NBLK - 1) {
            g_cnt = 0;
            __threadfence();
            g_gen = g + 1;
        } else {
            while (g_gen == g) __nanosleep(64);
        }
        __threadfence();
    }
    __syncthreads();
}

__device__ __forceinline__ float gatherA_gates(int t, int b, int k)
{
    if (k < EE)        return g_we[(size_t)(t * BB + b) * EE + k];
    if (k < EE + HH)   return __ldcg(&g_weighted[(b << 10) + (k - EE)]);
    if (k < XLEN)      return g_h0[(b << 10) + (k - (EE + HH))];
    return __ldcg(&g_h[(b << 10) + (k - XLEN)]);
}

__global__ __launch_bounds__(256)
void k_recur(const float* __restrict__ attnW, const float* __restrict__ v)
{
    __shared__ float w_s[8][32][4];
    __shared__ float a_s[16][36];
    __shared__ float attn_s[SS];
    __shared__ float red_s[8];

    const int bid = blockIdx.x;
    const int tid = threadIdx.x;
    const int lane = tid & 31;
    const int wid = tid >> 5;

    for (int t = 0; t < TT; t++) {
        // ---- phase A: hW = h @ Wh^T, split-K atomics (blocks 0..127) ----
        if (bid < 128) {
            int n0 = (bid & 31) * 32;
            int kbeg = (bid >> 5) * 256;
            int n_l = tid & 31, bq = tid >> 5;
            int wn = tid >> 3, wk = (tid & 7) * 4;
            float acc0 = 0.f, acc1 = 0.f;
            for (int k0 = kbeg; k0 < kbeg + 256; k0 += 32) {
                float4 wv = *(const float4*)&attnW[(size_t)(n0 + wn) * (2 * HH) + k0 + wk];
                int kk = tid & 31, bb = tid >> 5;
                float a0 = __ldcg(&g_h[(bb << 10) + k0 + kk]);
                float a1 = __ldcg(&g_h[((bb + 8) << 10) + k0 + kk]);
                __syncthreads();
                *(float4*)&w_s[wk >> 2][wn][0] = wv;
                a_s[bq][kk] = a0;
                a_s[bq + 8][kk] = a1;
                __syncthreads();
#pragma unroll
                for (int kg = 0; kg < 8; kg++) {
                    float4 w4 = *(const float4*)&w_s[kg][n_l][0];
                    float4 A0 = *(const float4*)&a_s[bq][kg * 4];
                    float4 A1 = *(const float4*)&a_s[bq + 8][kg * 4];
                    acc0 = fmaf(w4.x, A0.x, acc0); acc0 = fmaf(w4.y, A0.y, acc0);
                    acc0 = fmaf(w4.z, A0.z, acc0); acc0 = fmaf(w4.w, A0.w, acc0);
                    acc1 = fmaf(w4.x, A1.x, acc1); acc1 = fmaf(w4.y, A1.y, acc1);
                    acc1 = fmaf(w4.z, A1.z, acc1); acc1 = fmaf(w4.w, A1.w, acc1);
                }
            }
            atomicAdd(&g_hW[(bq << 10) + n0 + n_l], acc0);
            atomicAdd(&g_hW[((bq + 8) << 10) + n0 + n_l], acc1);
        }
        gbar();

        // ---- phase B: scores (all blocks, warp per (b,s) pair) ----
        for (int p = bid * 8 + wid; p < BB * SS; p += NBLK * 8) {
            int b = p >> 8, s = p & 255;
            const float* hsp = g_hsproj + ((size_t)(b * SS + s) << 10);
            const float* hw = g_hW + (b << 10);
            float acc = 0.f;
#pragma unroll 8
            for (int i = 0; i < 32; i++) {
                int k = lane + (i << 5);
                acc += v[k] * fast_tanh(__ldcg(&hw[k]) + hsp[k]);
            }
#pragma unroll
            for (int o = 16; o > 0; o >>= 1) acc += __shfl_xor_sync(0xffffffffu, acc, o);
            if (lane == 0) g_score[p] = acc;
        }
        gbar();

        // ---- phase C: softmax + weighted (blocks 0..63) ----
        if (bid < 64) {
            int b = bid >> 2;
            int hbase = (bid & 3) * 256;
            float sc = __ldcg(&g_score[b * SS + tid]);
            float m = sc;
#pragma unroll
            for (int o = 16; o > 0; o >>= 1) m = fmaxf(m, __shfl_xor_sync(0xffffffffu, m, o));
            if (lane == 0) red_s[wid] = m;
            __syncthreads();
            m = red_s[0];
#pragma unroll
            for (int w = 1; w < 8; w++) m = fmaxf(m, red_s[w]);
            float e = __expf(sc - m);
            float sum = e;
#pragma unroll
            for (int o = 16; o > 0; o >>= 1) sum += __shfl_xor_sync(0xffffffffu, sum, o);
            __syncthreads();
            attn_s[tid] = e;
            if (lane == 0) red_s[wid] = sum;
            __syncthreads();
            sum = 0.f;
#pragma unroll
            for (int w = 0; w < 8; w++) sum += red_s[w];
            float inv = __fdividef(1.0f, sum);

            int h = hbase + tid;
            const float* hv = g_hidden + ((size_t)(b * SS) << 10) + h;
            float a0 = 0.f, a1 = 0.f, a2 = 0.f, a3 = 0.f;
            for (int s = 0; s < SS; s += 4) {
                a0 = fmaf(attn_s[s],     hv[(size_t)s << 10],       a0);
                a1 = fmaf(attn_s[s + 1], hv[(size_t)(s + 1) << 10], a1);
                a2 = fmaf(attn_s[s + 2], hv[(size_t)(s + 2) << 10], a2);
                a3 = fmaf(attn_s[s + 3], hv[(size_t)(s + 3) << 10], a3);
            }
            float acc = ((a0 + a1) + (a2 + a3)) * inv;
            g_weighted[(b << 10) + h] = acc;
            g_Z[((size_t)(t * BB + b) << 11) + HH + h] = acc;
        }
        gbar();

        // ---- phase D: gates (blocks 0..127) ----
        if (bid < 128) {
            int n0 = bid * 32;
            int n_l = tid & 31, bq = tid >> 5;
            int wn = tid >> 3, wk = (tid & 7) * 4;
            float acc0 = 0.f, acc1 = 0.f;
            for (int k0 = 0; k0 < KG; k0 += 32) {
                float4 wv = *(const float4*)&g_Wcat[(size_t)(n0 + wn) * KG + k0 + wk];
                int kk = tid & 31, bb = tid >> 5;
                float a0 = gatherA_gates(t, bb, k0 + kk);
                float a1 = gatherA_gates(t, bb + 8, k0 + kk);
                __syncthreads();
                *(float4*)&w_s[wk >> 2][wn][0] = wv;
                a_s[bq][kk] = a0;
                a_s[bq + 8][kk] = a1;
                __syncthreads();
#pragma unroll
                for (int kg = 0; kg < 8; kg++) {
                    float4 w4 = *(const float4*)&w_s[kg][n_l][0];
                    float4 A0 = *(const float4*)&a_s[bq][kg * 4];
                    float4 A1 = *(const float4*)&a_s[bq + 8][kg * 4];
                    acc0 = fmaf(w4.x, A0.x, acc0); acc0 = fmaf(w4.y, A0.y, acc0);
                    acc0 = fmaf(w4.z, A0.z, acc0); acc0 = fmaf(w4.w, A0.w, acc0);
                    acc1 = fmaf(w4.x, A1.x, acc1); acc1 = fmaf(w4.y, A1.y, acc1);
                    acc1 = fmaf(w4.z, A1.z, acc1); acc1 = fmaf(w4.w, A1.w, acc1);
                }
            }
            float bsum = g_bias_sum[n0 + n_l];
            g_gates[bq * G4 + n0 + n_l]       = acc0 + bsum;
            g_gates[(bq + 8) * G4 + n0 + n_l] = acc1 + bsum;
        }
        gbar();

        // ---- phase E: LSTM cell (blocks 0..63) ----
        if (bid < 64) {
            int idx = (bid << 8) + tid;
            int b = idx >> 10, h = idx & 1023;
            const float* g = g_gates + b * G4;
            float ig = __ldcg(&g[h]);
            float fg = __ldcg(&g[HH + h]);
            float gg = __ldcg(&g[2 * HH + h]);
            float og = __ldcg(&g[3 * HH + h]);
            float c = fast_sig(fg) * g_c[idx] + fast_sig(ig) * fast_tanh(gg);
            float hn = fast_sig(og) * fast_tanh(c);
            g_c[idx] = c;
            g_h[idx] = hn;
            g_Z[((size_t)(t * BB + b) << 11) + h] = hn;
            g_hW[idx] = 0.0f;
        }
        gbar();
    }
}

// ---------------- host launch ----------------
extern "C" void kernel_launch(void* const* d_in, const int* in_sizes, int n_in,
                              void* d_out, int out_size)
{
    (void)in_sizes; (void)n_in; (void)out_size;
    const int*   inp    = (const int*)  d_in[0];
    const float* VQ     = (const float*)d_in[1];
    const float* embedW = (const float*)d_in[2];
    const float* transW = (const float*)d_in[3];
    const float* attnW  = (const float*)d_in[4];
    const float* attnb  = (const float*)d_in[5];
    const float* v      = (const float*)d_in[6];
    const float* W_ih   = (const float*)d_in[7];
    const float* W_hh   = (const float*)d_in[8];
    const float* b_ih   = (const float*)d_in[9];
    const float* b_hh   = (const float*)d_in[10];
    const float* predW  = (const float*)d_in[11];
    float* out = (float*)d_out;

    float *p_hidden, *p_hsproj, *p_Z;
    cudaGetSymbolAddress((void**)&p_hidden, g_hidden);
    cudaGetSymbolAddress((void**)&p_hsproj, g_hsproj);
    cudaGetSymbolAddress((void**)&p_Z,      g_Z);

    k_prep<<<2048, 256>>>(inp, embedW, W_ih, W_hh, b_ih, b_hh, out);
    k_biggemm<0, 0><<<dim3(32, 16), 256>>>(VQ, DQD, transW, DQD, 0, nullptr,
                                           p_hidden, HH, BB * SS, DQD);
    k_biggemm<1, 0><<<dim3(32, 16), 256>>>(p_hidden, HH, attnW, 2 * HH, HH, attnb,
                                           p_hsproj, HH, BB * SS, HH);
    k_init_h<<<64, 256>>>();

    // entire 255-step recurrence: ONE kernel, software grid barrier
    k_recur<<<NBLK, 256>>>(attnW, v);

    // hoisted logits GEMM (4080 x 32000, K=2048)
    k_biggemm<0, 1><<<dim3(32, 500), 256>>>(p_Z, 2 * HH, predW, 2 * HH, 0, nullptr,
                                            out, VV, TT * BB, 2 * HH);
}